// round 15
// baseline (speedup 1.0000x reference)
#include <cuda_runtime.h>
#include <cstdint>

#define NB 1024
#define NL 4096
// 2*log2(e)/tau and ln(2)
#define K2F  3.3945765667975607f
#define LN2F 0.6931471805599453f
#define FIXSCALE 4294967296.0   // 2^32

__device__ int  g_T[NB];
__device__ int4 g_bits[NB * 32];           // chunk c: 4 ballot words (m0..m3)
__device__ int  g_offs[NB * 32];           // label count before chunk c
__device__ unsigned long long g_acc = 0;   // fixed-point sum, self-resetting
__device__ unsigned g_count = 0;           // ticket, wraps via atomicInc

__device__ __forceinline__ float ex2f(float x) {
    float r;
    asm("ex2.approx.f32 %0, %1;" : "=f"(r) : "f"(x));
    return r;
}
__device__ __forceinline__ float lg2f(float x) {
    float r;
    asm("lg2.approx.f32 %0, %1;" : "=f"(r) : "f"(x));
    return r;
}

// ---- Pass A: stream labels once; emit bit-packed labels + chunk offsets + T ----
// Chunk c covers elements [c*128, c*128+128). Word m_j bit l = label[c*128 + 4*l + j].
__global__ __launch_bounds__(256)
void pack_kernel(const int* __restrict__ labels) {
    __shared__ int s_w[8], s_base[8];
    const int row  = blockIdx.x;
    const int t    = threadIdx.x;
    const int lane = t & 31;
    const int warp = t >> 5;               // 0..7; owns chunks 4w..4w+3

    const int4* lab4 = reinterpret_cast<const int4*>(labels + (size_t)row * NL) + warp * 128;

    int cs[4];
    int run = 0;
#pragma unroll
    for (int k = 0; k < 4; k++) {
        int4 a = lab4[k * 32 + lane];
        unsigned m0 = __ballot_sync(0xffffffffu, a.x);
        unsigned m1 = __ballot_sync(0xffffffffu, a.y);
        unsigned m2 = __ballot_sync(0xffffffffu, a.z);
        unsigned m3 = __ballot_sync(0xffffffffu, a.w);
        if (lane == 0)
            g_bits[row * 32 + warp * 4 + k] = make_int4((int)m0, (int)m1, (int)m2, (int)m3);
        cs[k] = run;
        run += __popc(m0) + __popc(m1) + __popc(m2) + __popc(m3);
    }
    if (lane == 0) s_w[warp] = run;
    __syncthreads();
    if (t == 0) {
        int base = 0;
#pragma unroll
        for (int w = 0; w < 8; w++) { s_base[w] = base; base += s_w[w]; }
        g_T[row] = base;
    }
    __syncthreads();
    if (lane < 4) {
        const int c = lane == 0 ? cs[0] : lane == 1 ? cs[1] : lane == 2 ? cs[2] : cs[3];
        g_offs[row * 32 + warp * 4 + lane] = s_base[warp] + c;
    }
}

// ---- Pass B: branchless math pass (integer count chain, split W accumulators) ----
__global__ __launch_bounds__(512)
void math_kernel(const float* __restrict__ probs, float* __restrict__ d_out) {
    __shared__ float s_S[16], s_W[16];

    const int row  = blockIdx.x;
    const int t    = threadIdx.x;
    const int lane = t & 31;
    const int warp = t >> 5;               // 0..15; owns chunks 2w, 2w+1

    const int T = g_T[row];                // issued first; gates kb only
    const float4* pr4 = reinterpret_cast<const float4*>(probs + (size_t)row * NL);

    int4   bv[2];
    float4 pv[2];
    int    ofs[2];
#pragma unroll
    for (int k = 0; k < 2; k++) {
        const int c = warp * 2 + k;
        bv[k]  = g_bits[row * 32 + c];     // warp-uniform broadcast LDG.128
        ofs[k] = g_offs[row * 32 + c];
        pv[k]  = pr4[c * 32 + lane];
    }

    const unsigned lt = (1u << lane) - 1u;
    float S0 = 0.0f, S1 = 0.0f;
    float Wf0 = 0.0f, Wf1 = 0.0f;          // sum e*f      (log2 units)
    float Wl0 = 0.0f, Wl1 = 0.0f;          // sum e*lg2(p)
#pragma unroll
    for (int k = 0; k < 2; k++) {
        const unsigned m0 = (unsigned)bv[k].x, m1 = (unsigned)bv[k].y;
        const unsigned m2 = (unsigned)bv[k].z, m3 = (unsigned)bv[k].w;
        // integer base count before (lane, j=0): never branches
        const int base = ofs[k] + __popc(m0 & lt) + __popc(m1 & lt)
                                + __popc(m2 & lt) + __popc(m3 & lt);
        // branchless bit chain (LOP+IADD only)
        const int b0 = (int)((m0 >> lane) & 1u);
        const int b1 = (int)((m1 >> lane) & 1u);
        const int b2 = (int)((m2 >> lane) & 1u);
        const int b3 = (int)((m3 >> lane) & 1u);
        const int c0 = base + b0;
        const int c1 = c0 + b1;
        const int c2 = c1 + b2;
        const int c3 = c2 + b3;

        const int   kb = (warp * 2 + k) * 128 + 4 * lane + 1 + T;   // idx+1+T
        const float r0 = __frcp_rn(1.0f / 1.0f) * 0.0f + __fdividef(1.0f, (float)kb); // RCP
        float kr0 = K2F * r0;                                       // folds 2*log2e/tau
        const float t1 = 1.0f * r0, t2 = 2.0f * r0, t3 = 3.0f * r0;
        const float kr1 = kr0 * __fmaf_rn(t1, t1, 1.0f - t1);       // Taylor 1/(kb+j)
        const float kr2 = kr0 * __fmaf_rn(t2, t2, 1.0f - t2);
        const float kr3 = kr0 * __fmaf_rn(t3, t3, 1.0f - t3);

        const float f0 = (float)c0 * kr0;   // I2F + FMUL, exactly 0 when c==0
        const float f1 = (float)c1 * kr1;
        const float f2 = (float)c2 * kr2;
        const float f3 = (float)c3 * kr3;

        const float e0 = ex2f(f0), e1 = ex2f(f1), e2 = ex2f(f2), e3 = ex2f(f3);
        const float l0 = lg2f(pv[k].x), l1 = lg2f(pv[k].y);
        const float l2 = lg2f(pv[k].z), l3 = lg2f(pv[k].w);

        S0 += e0; S1 += e1; S0 += e2; S1 += e3;
        Wf0 = __fmaf_rn(e0, f0, Wf0); Wf1 = __fmaf_rn(e1, f1, Wf1);
        Wf0 = __fmaf_rn(e2, f2, Wf0); Wf1 = __fmaf_rn(e3, f3, Wf1);
        Wl0 = __fmaf_rn(e0, l0, Wl0); Wl1 = __fmaf_rn(e1, l1, Wl1);
        Wl0 = __fmaf_rn(e2, l2, Wl0); Wl1 = __fmaf_rn(e3, l3, Wl1);
    }
    float S = S0 + S1;
    float W = (Wf0 + Wf1) - (Wl0 + Wl1);   // sum e*(f - lg2 p)

#pragma unroll
    for (int d = 16; d; d >>= 1) {
        S += __shfl_down_sync(0xffffffffu, S, d);
        W += __shfl_down_sync(0xffffffffu, W, d);
    }
    if (lane == 0) { s_S[warp] = S; s_W[warp] = W; }
    __syncthreads();
    if (t == 0) {
        float St = 0.0f, Wt = 0.0f;
#pragma unroll
        for (int w = 0; w < 16; w++) { St += s_S[w]; Wt += s_W[w]; }
        const float rv = LN2F * (Wt / St) - __logf(St);             // ln2*(W/S) - ln(S)
        const long long q32 = __float2ll_rn((double)rv * FIXSCALE);
        atomicAdd(&g_acc, (unsigned long long)q32);                 // integer: commutative
        __threadfence();
        unsigned ticket = atomicInc(&g_count, NB - 1);              // wraps after NB
        if (ticket == NB - 1) {
            __threadfence();
            const long long v = (long long)g_acc;
            d_out[0] = (float)((double)v * (1.0 / FIXSCALE) / (double)NB);
            g_acc = 0;                                              // reset for replay
        }
    }
}

extern "C" void kernel_launch(void* const* d_in, const int* in_sizes, int n_in,
                              void* d_out, int out_size) {
    const float* probs  = (const float*)d_in[0];   // output: (B, L, 1) f32
    const int*   labels = (const int*)d_in[1];     // labels: (B, L) i32
    pack_kernel<<<NB, 256>>>(labels);
    math_kernel<<<NB, 512>>>(probs, (float*)d_out);
}